// round 11
// baseline (speedup 1.0000x reference)
#include <cuda_runtime.h>
#include <math.h>

#define BATCH 8

// ---------------- scratch (device globals; no allocation allowed) ----------------
__device__ float g_C2[96 * 96];
__device__ float g_d2[96];
__device__ float g_M[128 * 128];    // collapsed affine matrix [o][k]
__device__ float g_Mt[128 * 128];   // transposed [k][o]
__device__ float g_d[128];          // collapsed bias

__device__ float g_pool1[BATCH * 32 * 128 * 128];
__device__ float g_pool2[BATCH * 32 * 64 * 64];
__device__ float g_pool3[BATCH * 32 * 32 * 32];

__device__ float g_s1[BATCH * 32 * 128 * 128];
__device__ float g_s2[BATCH * 32 * 64 * 64];
__device__ float g_s3[BATCH * 32 * 32 * 32];

__device__ float g_P3[BATCH * 128 * 32 * 32];
__device__ float g_P2[BATCH * 128 * 64 * 64];
__device__ float g_P1[BATCH * 128 * 128 * 128];   // referenced by template only

// ---------------- f32x2 packed helpers ----------------
__device__ __forceinline__ unsigned long long pk2(float lo, float hi) {
    unsigned long long r;
    asm("mov.b64 %0, {%1,%2};" : "=l"(r) : "f"(lo), "f"(hi));
    return r;
}
__device__ __forceinline__ unsigned long long dup2(float v) { return pk2(v, v); }
__device__ __forceinline__ unsigned long long fma2(unsigned long long a, unsigned long long b,
                                                   unsigned long long c) {
    unsigned long long r;
    asm("fma.rn.f32x2 %0, %1, %2, %3;" : "=l"(r) : "l"(a), "l"(b), "l"(c));
    return r;
}
__device__ __forceinline__ float2 upk2(unsigned long long v) {
    float2 f;
    asm("mov.b64 {%0,%1}, %2;" : "=f"(f.x), "=f"(f.y) : "l"(v));
    return f;
}

// ---------------- tf32 helpers ----------------
__device__ __forceinline__ unsigned f2tf(float f) {
    unsigned r;
    asm("cvt.rna.tf32.f32 %0, %1;" : "=r"(r) : "f"(f));
    return r;
}
__device__ __forceinline__ void mma_tf32(float& c0, float& c1, float& c2, float& c3,
                                         unsigned a0, unsigned a1, unsigned a2, unsigned a3,
                                         unsigned b0, unsigned b1) {
    asm volatile(
        "mma.sync.aligned.m16n8k8.row.col.f32.tf32.tf32.f32 "
        "{%0,%1,%2,%3}, {%4,%5,%6,%7}, {%8,%9}, {%0,%1,%2,%3};"
        : "+f"(c0), "+f"(c1), "+f"(c2), "+f"(c3)
        : "r"(a0), "r"(a1), "r"(a2), "r"(a3), "r"(b0), "r"(b1));
}

// ---------------- fast erf (A&S 7.1.26, |abs err| <= 1.5e-7) ----------------
__device__ __forceinline__ float fast_erf(float x) {
    float ax = fabsf(x);
    float t = __frcp_rn(fmaf(0.3275911f, ax, 1.0f));
    float y = t * fmaf(t, fmaf(t, fmaf(t, fmaf(t, 1.061405429f, -1.453152027f),
                                       1.421413741f), -0.284496736f), 0.254829592f);
    float r = 1.0f - y * __expf(-ax * ax);
    return copysignf(r, x);
}
__device__ __forceinline__ float gelu_mul(float a, float xv) {
    return 0.5f * a * (1.0f + fast_erf(a * 0.70710678118654752f)) * xv;
}

// ---------------- setup: collapse shuffle+concat+pw chain into M, Mt, d ----------------
__global__ void setup1_kernel(const float* __restrict__ w1, const float* __restrict__ b1,
                              const float* __restrict__ w2, const float* __restrict__ b2) {
    int o = blockIdx.x;    // 0..95
    int j = threadIdx.x;   // 0..95
    float acc;
    if (j < 64) {
        acc = 0.f;
        for (int k = 0; k < 64; k++) {
            float b2v = w2[o * 96 + (k % 12) * 8 + k / 12];
            float a1v = w1[k * 64 + (j % 8) * 8 + j / 8];
            acc = fmaf(b2v, a1v, acc);
        }
    } else {
        acc = w2[o * 96 + (j % 12) * 8 + j / 12];
    }
    g_C2[o * 96 + j] = acc;
    if (j == 0) {
        float s = b2[o];
        for (int k = 0; k < 64; k++)
            s = fmaf(w2[o * 96 + (k % 12) * 8 + k / 12], b1[k], s);
        g_d2[o] = s;
    }
}

__global__ void setup2_kernel(const float* __restrict__ w3, const float* __restrict__ b3) {
    int o = blockIdx.x;    // 0..127
    int j = threadIdx.x;   // 0..127
    float acc;
    if (j < 96) {
        acc = 0.f;
        for (int k = 0; k < 96; k++)
            acc = fmaf(w3[o * 128 + (k % 16) * 8 + k / 16], g_C2[k * 96 + j], acc);
    } else {
        acc = w3[o * 128 + (j % 16) * 8 + j / 16];
    }
    g_M[o * 128 + j] = acc;
    g_Mt[j * 128 + o] = acc;
    if (j == 0) {
        float s = b3[o];
        for (int k = 0; k < 96; k++)
            s = fmaf(w3[o * 128 + (k % 16) * 8 + k / 16], g_d2[k], s);
        g_d[o] = s;
    }
}

// ---------------- vectorized max pools ----------------
__global__ void pool1_kernel(const float* __restrict__ x) {  // k=2, HO=128
    int idx = blockIdx.x * blockDim.x + threadIdx.x;
    const int TOT = BATCH * 32 * 128 * 64;
    if (idx >= TOT) return;
    int wp = idx & 63;
    int t = idx >> 6;
    int ho = t & 127; t >>= 7;
    int c = t & 31;
    int b = t >> 5;
    const float* src = x + ((size_t)(b * 128 + 32 + c) * 256 + (size_t)ho * 2) * 256 + (size_t)wp * 4;
    float4 r0 = *(const float4*)src;
    float4 r1 = *(const float4*)(src + 256);
    float2 o2;
    o2.x = fmaxf(fmaxf(r0.x, r0.y), fmaxf(r1.x, r1.y));
    o2.y = fmaxf(fmaxf(r0.z, r0.w), fmaxf(r1.z, r1.w));
    *(float2*)&g_pool1[(size_t)idx * 2] = o2;
}

__global__ void pool2_kernel(const float* __restrict__ x) {  // k=4, HO=64
    int idx = blockIdx.x * blockDim.x + threadIdx.x;
    const int TOT = BATCH * 32 * 64 * 64;
    if (idx >= TOT) return;
    int wo = idx & 63;
    int t = idx >> 6;
    int ho = t & 63; t >>= 6;
    int c = t & 31;
    int b = t >> 5;
    const float* src = x + ((size_t)(b * 128 + 64 + c) * 256 + (size_t)ho * 4) * 256 + (size_t)wo * 4;
    float m = -3.402823466e38f;
#pragma unroll
    for (int r = 0; r < 4; r++) {
        float4 v = *(const float4*)(src + r * 256);
        m = fmaxf(m, fmaxf(fmaxf(v.x, v.y), fmaxf(v.z, v.w)));
    }
    g_pool2[idx] = m;
}

__global__ void pool3_kernel(const float* __restrict__ x) {  // k=8, HO=32
    int idx = blockIdx.x * blockDim.x + threadIdx.x;
    const int TOT = BATCH * 32 * 32 * 32;
    if (idx >= TOT) return;
    int wo = idx & 31;
    int t = idx >> 5;
    int ho = t & 31; t >>= 5;
    int c = t & 31;
    int b = t >> 5;
    const float* src = x + ((size_t)(b * 128 + 96 + c) * 256 + (size_t)ho * 8) * 256 + (size_t)wo * 8;
    float m = -3.402823466e38f;
#pragma unroll
    for (int r = 0; r < 8; r++) {
        float4 v0 = *(const float4*)(src + r * 256);
        float4 v1 = *(const float4*)(src + r * 256 + 4);
        m = fmaxf(m, fmaxf(fmaxf(v0.x, v0.y), fmaxf(v0.z, v0.w)));
        m = fmaxf(m, fmaxf(fmaxf(v1.x, v1.y), fmaxf(v1.z, v1.w)));
    }
    g_pool3[idx] = m;
}

// ---------------- depthwise 3x3 conv (levels 1-3), 4 outputs per thread ----------------
template <int LEVEL, int H>
__global__ void dw_kernel(const float* __restrict__ w_dw, const float* __restrict__ b_dw) {
    const float* in = (LEVEL == 1) ? (const float*)g_pool1
                    : (LEVEL == 2) ? (const float*)g_pool2
                                   : (const float*)g_pool3;
    float* out = (LEVEL == 1) ? g_s1 : (LEVEL == 2) ? g_s2 : g_s3;
    int idx = blockIdx.x * blockDim.x + threadIdx.x;
    constexpr int W4 = H / 4;
    constexpr int TOT = BATCH * 32 * H * W4;
    if (idx >= TOT) return;
    int w4 = (idx % W4) * 4;
    int t = idx / W4;
    int h = t % H; t /= H;
    int c = t & 31;
    int b = t >> 5;
    const float* wp = w_dw + (LEVEL * 32 + c) * 9;
    float w00 = wp[0], w01 = wp[1], w02 = wp[2];
    float w10 = wp[3], w11 = wp[4], w12 = wp[5];
    float w20 = wp[6], w21 = wp[7], w22 = wp[8];
    float bias = b_dw[LEVEL * 32 + c];
    float a0 = bias, a1 = bias, a2 = bias, a3 = bias;
    const float* base = in + (size_t)(b * 32 + c) * H * H;
#pragma unroll
    for (int dy = -1; dy <= 1; dy++) {
        int hy = h + dy;
        if (hy < 0 || hy >= H) continue;
        const float* row = base + (size_t)hy * H;
        float4 C = *(const float4*)(row + w4);
        float lft = (w4 > 0) ? row[w4 - 1] : 0.f;
        float rgt = (w4 + 4 < H) ? row[w4 + 4] : 0.f;
        float k0 = (dy == -1) ? w00 : (dy == 0) ? w10 : w20;
        float k1 = (dy == -1) ? w01 : (dy == 0) ? w11 : w21;
        float k2 = (dy == -1) ? w02 : (dy == 0) ? w12 : w22;
        a0 = fmaf(k0, lft, fmaf(k1, C.x, fmaf(k2, C.y, a0)));
        a1 = fmaf(k0, C.x, fmaf(k1, C.y, fmaf(k2, C.z, a1)));
        a2 = fmaf(k0, C.y, fmaf(k1, C.z, fmaf(k2, C.w, a2)));
        a3 = fmaf(k0, C.z, fmaf(k1, C.w, fmaf(k2, rgt, a3)));
    }
    float4 r;
    r.x = a0; r.y = a1; r.z = a2; r.w = a3;
    *(float4*)&out[(size_t)idx * 4] = r;
}

// ---------------- tiled 128x32 GEMM + up2 accumulate (cascade levels 2..3) ----------------
template <int LEVEL, int H>
__global__ void gemm_tiled() {
    constexpr int PIX = H * H;
    constexpr int CPIX = PIX / 4;
    constexpr int CP = (H >= 64) ? 32 : 16;
    const float* S = (LEVEL == 3) ? g_s3 : (LEVEL == 2) ? g_s2 : g_s1;
    const float* Pprev = (LEVEL == 2) ? (const float*)g_P3 : (const float*)g_P2;
    float* Pout = (LEVEL == 3) ? g_P3 : (LEVEL == 2) ? g_P2 : g_P1;

    __shared__ float Msm[32 * 128];
    __shared__ float Ssm[32 * 64];
    __shared__ float Psm[128 * CP];

    int blk = blockIdx.x;
    int b = blk / (PIX / 64);
    int hw0 = (blk % (PIX / 64)) * 64;
    int tid = threadIdx.x;

    for (int i = tid * 4; i < 32 * 128; i += 512)
        *(float4*)&Msm[i] = *(const float4*)&g_Mt[(LEVEL * 32 + (i >> 7)) * 128 + (i & 127)];
    for (int i = tid * 4; i < 32 * 64; i += 512) {
        int k = i >> 6, p = i & 63;
        *(float4*)&Ssm[i] = *(const float4*)&S[(size_t)(b * 32 + k) * PIX + hw0 + p];
    }
    if (LEVEL < 3) {
        int h = hw0 / H;
        int w0 = hw0 % H;
        int cbase = (h >> 1) * (H / 2) + (w0 >> 1);
        for (int i = tid * 4; i < 128 * CP; i += 512) {
            int o = i / CP, cp = i % CP;
            *(float4*)&Psm[i] = *(const float4*)&Pprev[(size_t)(b * 128 + o) * CPIX + cbase + cp];
        }
    }
    __syncthreads();

    int to = tid >> 3;
    int tp = tid & 7;

    unsigned long long acc[8][4];
#pragma unroll
    for (int i = 0; i < 8; i++)
#pragma unroll
        for (int j = 0; j < 4; j++) acc[i][j] = 0ULL;

#pragma unroll 4
    for (int k = 0; k < 32; k++) {
        float4 ma = *(const float4*)&Msm[k * 128 + to * 8];
        float4 mb = *(const float4*)&Msm[k * 128 + to * 8 + 4];
        float4 sa = *(const float4*)&Ssm[k * 64 + tp * 8];
        float4 sb = *(const float4*)&Ssm[k * 64 + tp * 8 + 4];
        unsigned long long sp[4] = {pk2(sa.x, sa.y), pk2(sa.z, sa.w),
                                    pk2(sb.x, sb.y), pk2(sb.z, sb.w)};
        float mv[8] = {ma.x, ma.y, ma.z, ma.w, mb.x, mb.y, mb.z, mb.w};
#pragma unroll
        for (int o8 = 0; o8 < 8; o8++) {
            unsigned long long md = dup2(mv[o8]);
#pragma unroll
            for (int pp = 0; pp < 4; pp++) acc[o8][pp] = fma2(sp[pp], md, acc[o8][pp]);
        }
    }

    int cpb = (H >= 64) ? tp * 4 : (tp & 3) * 4;
#pragma unroll
    for (int o8 = 0; o8 < 8; o8++) {
        int o = to * 8 + o8;
        float p0 = 0.f, p1 = 0.f, p2 = 0.f, p3 = 0.f;
        if (LEVEL < 3) {
            p0 = Psm[o * CP + cpb + 0];
            p1 = Psm[o * CP + cpb + 1];
            p2 = Psm[o * CP + cpb + 2];
            p3 = Psm[o * CP + cpb + 3];
        }
        float2 v0 = upk2(acc[o8][0]), v1 = upk2(acc[o8][1]);
        float2 v2 = upk2(acc[o8][2]), v3 = upk2(acc[o8][3]);
        float4 r0, r1;
        r0.x = v0.x + p0; r0.y = v0.y + p0; r0.z = v1.x + p1; r0.w = v1.y + p1;
        r1.x = v2.x + p2; r1.y = v2.y + p2; r1.z = v3.x + p3; r1.w = v3.y + p3;
        float* dst = Pout + (size_t)(b * 128 + o) * PIX + hw0 + tp * 8;
        *(float4*)dst = r0;
        *(float4*)(dst + 4) = r1;
    }
}

// ---------------- final (tensor cores; dw0 AND level-1 coarse GEMM fused in) ----------------
// Tile = 2 fine rows x 64 cols (128 px) -> 1 coarse row x 32 cols. 256 thr (8 warps).
// Phase 0: dw0 on x ch0-31 computed per-thread (row-streamed, vectorized) -> Sfine (tf32).
// Phase A: coarse GEMM P = M1*s1 + up2(P2) + d -> Psm[128][34].
// Phase B: fine GEMM M0*s0 (tf32 MMA) + Psm, gelu, * x, store.
__global__ __launch_bounds__(256) void final_mma(const float* __restrict__ x,
                                                 const float* __restrict__ w_dw,
                                                 const float* __restrict__ b_dw,
                                                 float* __restrict__ out) {
    __shared__ unsigned Sfine[32 * 132];
    __shared__ unsigned Scrs[32 * 36];
    __shared__ float Psm[128 * 34];

    int blk = blockIdx.x;
    int b = blk >> 9;              // 512 tiles per batch
    int rem = blk & 511;
    int h0 = (rem >> 2) * 2;       // even fine-row pair
    int w0 = (rem & 3) * 64;       // 64-col strip
    int tid = threadIdx.x;

    // ---------- Phase 0: dw0 -> Sfine (tf32), one (channel, row, 16-col) job/thread ----------
    {
        int c = tid >> 3;            // 0..31
        int sub = tid & 7;
        int r = sub >> 2;            // row within tile
        int cc0 = (sub & 3) * 16;    // col segment within strip
        int h = h0 + r;
        int base = w0 + cc0;         // 16-aligned global col
        const float* xb = x + (((size_t)(b * 128 + c)) << 16);
        const float* wp = w_dw + c * 9;
        float wk[9];
#pragma unroll
        for (int i = 0; i < 9; i++) wk[i] = wp[i];
        float acc[16];
        float bias = b_dw[c];
#pragma unroll
        for (int j = 0; j < 16; j++) acc[j] = bias;

#pragma unroll
        for (int dy = 0; dy < 3; dy++) {
            int hy = h + dy - 1;
            if (hy >= 0 && hy < 256) {
                const float* row = xb + ((size_t)hy << 8);
                float v[18];
                v[0] = (base > 0) ? row[base - 1] : 0.f;
                float4 C0 = *(const float4*)(row + base);
                float4 C1 = *(const float4*)(row + base + 4);
                float4 C2 = *(const float4*)(row + base + 8);
                float4 C3 = *(const float4*)(row + base + 12);
                v[1] = C0.x;  v[2] = C0.y;  v[3] = C0.z;  v[4] = C0.w;
                v[5] = C1.x;  v[6] = C1.y;  v[7] = C1.z;  v[8] = C1.w;
                v[9] = C2.x;  v[10] = C2.y; v[11] = C2.z; v[12] = C2.w;
                v[13] = C3.x; v[14] = C3.y; v[15] = C3.z; v[16] = C3.w;
                v[17] = (base + 16 < 256) ? row[base + 16] : 0.f;
                float k0 = wk[dy * 3 + 0], k1 = wk[dy * 3 + 1], k2 = wk[dy * 3 + 2];
#pragma unroll
                for (int j = 0; j < 16; j++)
                    acc[j] = fmaf(k0, v[j], fmaf(k1, v[j + 1], fmaf(k2, v[j + 2], acc[j])));
            }
        }
        unsigned* dst = &Sfine[c * 132 + r * 64 + cc0];
#pragma unroll
        for (int j = 0; j < 16; j++) dst[j] = f2tf(acc[j]);
    }

    // stage coarse s1 patch (row h0/2, cols w0/2..+31) -> tf32
    {
        int hc = h0 >> 1, wc0 = w0 >> 1;
        for (int i = tid * 4; i < 32 * 32; i += 1024) {
            int k = i >> 5, cl = i & 31;
            float4 v = *(const float4*)&g_s1[(((size_t)(b * 32 + k)) << 14) +
                                             (size_t)hc * 128 + wc0 + cl];
            unsigned* dst = &Scrs[k * 36 + cl];
            dst[0] = f2tf(v.x); dst[1] = f2tf(v.y); dst[2] = f2tf(v.z); dst[3] = f2tf(v.w);
        }
    }
    __syncthreads();

    int lane = tid & 31;
    int warp = tid >> 5;
    int ow = warp << 4;            // 16 outputs per warp
    int r = lane >> 2;             // 0..7
    int q = lane & 3;              // 0..3
    int oa = ow + r, ob = oa + 8;

    // ---------- Phase A: coarse GEMM (M columns 32..63 vs s1) ----------
    {
        unsigned ac[4][4];
#pragma unroll
        for (int kk = 0; kk < 4; kk++) {
            const float* m0 = &g_M[oa * 128 + 32 + kk * 8 + q];
            const float* m1 = &g_M[ob * 128 + 32 + kk * 8 + q];
            ac[kk][0] = f2tf(m0[0]);
            ac[kk][1] = f2tf(m1[0]);
            ac[kk][2] = f2tf(m0[4]);
            ac[kk][3] = f2tf(m1[4]);
        }
        float dva = g_d[oa], dvb = g_d[ob];
        int r2 = h0 >> 2;                       // coarse2 row
        int c2b = (w0 >> 2) + q;                // coarse2 col base for this lane
        size_t p2a = ((size_t)(b * 128 + oa) << 12) + (size_t)r2 * 64 + c2b;
        size_t p2b = ((size_t)(b * 128 + ob) << 12) + (size_t)r2 * 64 + c2b;
#pragma unroll
        for (int nc = 0; nc < 4; nc++) {
            float c0 = 0.f, c1 = 0.f, c2 = 0.f, c3 = 0.f;
#pragma unroll
            for (int kk = 0; kk < 4; kk++) {
                unsigned b0 = Scrs[(kk * 8 + q) * 36 + nc * 8 + r];
                unsigned b1 = Scrs[(kk * 8 + 4 + q) * 36 + nc * 8 + r];
                mma_tf32(c0, c1, c2, c3, ac[kk][0], ac[kk][1], ac[kk][2], ac[kk][3], b0, b1);
            }
            float pa = g_P2[p2a + nc * 4] + dva;   // both children share coarse2 parent
            float pb = g_P2[p2b + nc * 4] + dvb;
            float2 va, vb;
            va.x = c0 + pa; va.y = c1 + pa;
            vb.x = c2 + pb; vb.y = c3 + pb;
            *(float2*)&Psm[oa * 34 + nc * 8 + q * 2] = va;
            *(float2*)&Psm[ob * 34 + nc * 8 + q * 2] = vb;
        }
    }

    // A fragments for fine GEMM (M columns 0..31)
    unsigned a[4][4];
#pragma unroll
    for (int kk = 0; kk < 4; kk++) {
        const float* m0 = &g_M[oa * 128 + kk * 8 + q];
        const float* m1 = &g_M[ob * 128 + kk * 8 + q];
        a[kk][0] = f2tf(m0[0]);
        a[kk][1] = f2tf(m1[0]);
        a[kk][2] = f2tf(m0[4]);
        a[kk][3] = f2tf(m1[4]);
    }
    __syncthreads();

    // ---------- Phase B: fine GEMM + epilogue ----------
    size_t xbase_a = (((size_t)(b * 128 + oa)) << 16);
    size_t xbase_b = (((size_t)(b * 128 + ob)) << 16);

#pragma unroll 4
    for (int n = 0; n < 16; n++) {
        float c0 = 0.f, c1 = 0.f, c2 = 0.f, c3 = 0.f;
#pragma unroll
        for (int kk = 0; kk < 4; kk++) {
            unsigned b0 = Sfine[(kk * 8 + q) * 132 + n * 8 + r];
            unsigned b1 = Sfine[(kk * 8 + 4 + q) * 132 + n * 8 + r];
            mma_tf32(c0, c1, c2, c3, a[kk][0], a[kk][1], a[kk][2], a[kk][3], b0, b1);
        }
        int rowb = n >> 3;                       // fine row within tile
        int coln = (n & 7) * 8 + q * 2;          // fine col within strip (even)
        size_t roff = (size_t)(h0 + rowb) * 256 + w0 + coln;
        float pa = Psm[oa * 34 + (n & 7) * 4 + q];   // coarse col = coln/2
        float pb = Psm[ob * 34 + (n & 7) * 4 + q];
        float2 xa = *(const float2*)&x[xbase_a + roff];
        float2 xb = *(const float2*)&x[xbase_b + roff];
        float2 ra, rb;
        ra.x = gelu_mul(c0 + pa, xa.x);
        ra.y = gelu_mul(c1 + pa, xa.y);
        rb.x = gelu_mul(c2 + pb, xb.x);
        rb.y = gelu_mul(c3 + pb, xb.y);
        *(float2*)&out[xbase_a + roff] = ra;
        *(float2*)&out[xbase_b + roff] = rb;
    }
}

// ---------------- launch ----------------
extern "C" void kernel_launch(void* const* d_in, const int* in_sizes, int n_in,
                              void* d_out, int out_size) {
    const float* x   = (const float*)d_in[0];
    const float* wdw = (const float*)d_in[1];
    const float* bdw = (const float*)d_in[2];
    const float* w1  = (const float*)d_in[3];
    const float* b1  = (const float*)d_in[4];
    const float* w2  = (const float*)d_in[5];
    const float* b2  = (const float*)d_in[6];
    const float* w3  = (const float*)d_in[7];
    const float* b3  = (const float*)d_in[8];
    float* out = (float*)d_out;

    setup1_kernel<<<96, 96>>>(w1, b1, w2, b2);
    setup2_kernel<<<128, 128>>>(w3, b3);

    pool1_kernel<<<(BATCH * 32 * 128 * 64 + 255) / 256, 256>>>(x);
    pool2_kernel<<<(BATCH * 32 * 64 * 64 + 255) / 256, 256>>>(x);
    pool3_kernel<<<(BATCH * 32 * 32 * 32 + 255) / 256, 256>>>(x);

    dw_kernel<1, 128><<<(BATCH * 32 * 128 * 32 + 255) / 256, 256>>>(wdw, bdw);
    dw_kernel<2, 64><<<(BATCH * 32 * 64 * 16 + 255) / 256, 256>>>(wdw, bdw);
    dw_kernel<3, 32><<<(BATCH * 32 * 32 * 8 + 255) / 256, 256>>>(wdw, bdw);

    gemm_tiled<3, 32><<<BATCH * (32 * 32 / 64), 128>>>();
    gemm_tiled<2, 64><<<BATCH * (64 * 64 / 64), 128>>>();

    final_mma<<<BATCH * 512, 256>>>(x, wdw, bdw, out);
}

// round 14
// speedup vs baseline: 1.0304x; 1.0304x over previous
#include <cuda_runtime.h>
#include <math.h>

#define BATCH 8

// ---------------- scratch (device globals; no allocation allowed) ----------------
__device__ float g_C2[96 * 96];
__device__ float g_d2[96];
__device__ float g_M[128 * 128];    // collapsed affine matrix [o][k]
__device__ float g_Mt[128 * 128];   // transposed [k][o]
__device__ float g_d[128];          // collapsed bias

__device__ float g_s1[BATCH * 32 * 128 * 128];
__device__ float g_s2[BATCH * 32 * 64 * 64];
__device__ float g_s3[BATCH * 32 * 32 * 32];

__device__ float g_P3[BATCH * 128 * 32 * 32];
__device__ float g_P2[BATCH * 128 * 64 * 64];
__device__ float g_P1[1];   // referenced by gemm_tiled ternary only (never written/read)

// ---------------- f32x2 packed helpers ----------------
__device__ __forceinline__ unsigned long long pk2(float lo, float hi) {
    unsigned long long r;
    asm("mov.b64 %0, {%1,%2};" : "=l"(r) : "f"(lo), "f"(hi));
    return r;
}
__device__ __forceinline__ unsigned long long dup2(float v) { return pk2(v, v); }
__device__ __forceinline__ unsigned long long fma2(unsigned long long a, unsigned long long b,
                                                   unsigned long long c) {
    unsigned long long r;
    asm("fma.rn.f32x2 %0, %1, %2, %3;" : "=l"(r) : "l"(a), "l"(b), "l"(c));
    return r;
}
__device__ __forceinline__ float2 upk2(unsigned long long v) {
    float2 f;
    asm("mov.b64 {%0,%1}, %2;" : "=f"(f.x), "=f"(f.y) : "l"(v));
    return f;
}

// ---------------- tf32 helpers ----------------
__device__ __forceinline__ unsigned f2tf(float f) {
    unsigned r;
    asm("cvt.rna.tf32.f32 %0, %1;" : "=r"(r) : "f"(f));
    return r;
}
__device__ __forceinline__ void mma_tf32(float& c0, float& c1, float& c2, float& c3,
                                         unsigned a0, unsigned a1, unsigned a2, unsigned a3,
                                         unsigned b0, unsigned b1) {
    asm volatile(
        "mma.sync.aligned.m16n8k8.row.col.f32.tf32.tf32.f32 "
        "{%0,%1,%2,%3}, {%4,%5,%6,%7}, {%8,%9}, {%0,%1,%2,%3};"
        : "+f"(c0), "+f"(c1), "+f"(c2), "+f"(c3)
        : "r"(a0), "r"(a1), "r"(a2), "r"(a3), "r"(b0), "r"(b1));
}

// ---------------- fast erf (A&S 7.1.26, |abs err| <= 1.5e-7) ----------------
__device__ __forceinline__ float fast_erf(float x) {
    float ax = fabsf(x);
    float t = __frcp_rn(fmaf(0.3275911f, ax, 1.0f));
    float y = t * fmaf(t, fmaf(t, fmaf(t, fmaf(t, 1.061405429f, -1.453152027f),
                                       1.421413741f), -0.284496736f), 0.254829592f);
    float r = 1.0f - y * __expf(-ax * ax);
    return copysignf(r, x);
}
__device__ __forceinline__ float gelu_mul(float a, float xv) {
    return 0.5f * a * (1.0f + fast_erf(a * 0.70710678118654752f)) * xv;
}

// ---------------- setup: collapse shuffle+concat+pw chain into M, Mt, d ----------------
__global__ void setup1_kernel(const float* __restrict__ w1, const float* __restrict__ b1,
                              const float* __restrict__ w2, const float* __restrict__ b2) {
    int o = blockIdx.x;    // 0..95
    int j = threadIdx.x;   // 0..95
    float acc;
    if (j < 64) {
        acc = 0.f;
        for (int k = 0; k < 64; k++) {
            float b2v = w2[o * 96 + (k % 12) * 8 + k / 12];
            float a1v = w1[k * 64 + (j % 8) * 8 + j / 8];
            acc = fmaf(b2v, a1v, acc);
        }
    } else {
        acc = w2[o * 96 + (j % 12) * 8 + j / 12];
    }
    g_C2[o * 96 + j] = acc;
    if (j == 0) {
        float s = b2[o];
        for (int k = 0; k < 64; k++)
            s = fmaf(w2[o * 96 + (k % 12) * 8 + k / 12], b1[k], s);
        g_d2[o] = s;
    }
}

__global__ void setup2_kernel(const float* __restrict__ w3, const float* __restrict__ b3) {
    int o = blockIdx.x;    // 0..127
    int j = threadIdx.x;   // 0..127
    float acc;
    if (j < 96) {
        acc = 0.f;
        for (int k = 0; k < 96; k++)
            acc = fmaf(w3[o * 128 + (k % 16) * 8 + k / 16], g_C2[k * 96 + j], acc);
    } else {
        acc = w3[o * 128 + (j % 16) * 8 + j / 16];
    }
    g_M[o * 128 + j] = acc;
    g_Mt[j * 128 + o] = acc;
    if (j == 0) {
        float s = b3[o];
        for (int k = 0; k < 96; k++)
            s = fmaf(w3[o * 128 + (k % 16) * 8 + k / 16], g_d2[k], s);
        g_d[o] = s;
    }
}

// ---------------- fused max-pool(KxK) + depthwise 3x3 (levels 1-3) ----------------
// Block: 256 thr, one (b, c) channel, TR=8 pooled output rows (full width HO).
// Stage pooled rows [tr-1 .. tr+8] (zero outside) in smem, then dw 3x3 in-block.
template <int LEVEL, int K, int HO>
__global__ __launch_bounds__(256) void pooldw_kernel(const float* __restrict__ x,
                                                     const float* __restrict__ w_dw,
                                                     const float* __restrict__ b_dw) {
    constexpr int TR = 8;
    constexpr int OPT = TR * HO / 256;
    __shared__ float sm[(TR + 2) * HO];
    float* out = (LEVEL == 1) ? g_s1 : (LEVEL == 2) ? g_s2 : g_s3;
    int t = blockIdx.x;
    int rb = t % (HO / TR); t /= (HO / TR);
    int c = t & 31;
    int b = t >> 5;
    int tid = threadIdx.x;
    const float* xb = x + (((size_t)(b * 128 + LEVEL * 32 + c)) << 16);

    for (int i = tid; i < (TR + 2) * HO; i += 256) {
        int li = i / HO;
        int pc = i % HO;
        int pr = rb * TR + li - 1;
        float m = 0.f;                       // zero pad outside image (matches SAME conv)
        if (pr >= 0 && pr < HO) {
            m = -3.402823466e38f;
            const float* src = xb + (size_t)(pr * K) * 256 + pc * K;
            if (K == 2) {
                float2 a0 = *(const float2*)src;
                float2 a1 = *(const float2*)(src + 256);
                m = fmaxf(fmaxf(a0.x, a0.y), fmaxf(a1.x, a1.y));
            } else if (K == 4) {
#pragma unroll
                for (int r = 0; r < 4; r++) {
                    float4 v = *(const float4*)(src + r * 256);
                    m = fmaxf(m, fmaxf(fmaxf(v.x, v.y), fmaxf(v.z, v.w)));
                }
            } else {
#pragma unroll
                for (int r = 0; r < 8; r++) {
                    float4 v0 = *(const float4*)(src + r * 256);
                    float4 v1 = *(const float4*)(src + r * 256 + 4);
                    m = fmaxf(m, fmaxf(fmaxf(v0.x, v0.y), fmaxf(v0.z, v0.w)));
                    m = fmaxf(m, fmaxf(fmaxf(v1.x, v1.y), fmaxf(v1.z, v1.w)));
                }
            }
        }
        sm[i] = m;
    }
    __syncthreads();

    const float* wp = w_dw + (LEVEL * 32 + c) * 9;
    float w00 = wp[0], w01 = wp[1], w02 = wp[2];
    float w10 = wp[3], w11 = wp[4], w12 = wp[5];
    float w20 = wp[6], w21 = wp[7], w22 = wp[8];
    float bias = b_dw[LEVEL * 32 + c];

    int idx0 = tid * OPT;
    int rr = idx0 / HO;
    int cc = idx0 % HO;
    float res[OPT];
#pragma unroll
    for (int j = 0; j < OPT; j++) {
        int ccj = cc + j;
        float acc = bias;
#pragma unroll
        for (int dy = 0; dy < 3; dy++) {
            const float* row = &sm[(rr + dy) * HO];
            float k0 = (dy == 0) ? w00 : (dy == 1) ? w10 : w20;
            float k1 = (dy == 0) ? w01 : (dy == 1) ? w11 : w21;
            float k2 = (dy == 0) ? w02 : (dy == 1) ? w12 : w22;
            float lf = (ccj > 0) ? row[ccj - 1] : 0.f;
            float cm = row[ccj];
            float rg = (ccj + 1 < HO) ? row[ccj + 1] : 0.f;
            acc = fmaf(k0, lf, fmaf(k1, cm, fmaf(k2, rg, acc)));
        }
        res[j] = acc;
    }
    int hglob = rb * TR + rr;
    float* dst = &out[((size_t)(b * 32 + c) * HO + hglob) * HO + cc];
#pragma unroll
    for (int j = 0; j < OPT; j++) dst[j] = res[j];
}

// ---------------- tiled 128x32 GEMM + up2 accumulate (cascade levels 2..3) ----------------
template <int LEVEL, int H>
__global__ void gemm_tiled() {
    constexpr int PIX = H * H;
    constexpr int CPIX = PIX / 4;
    constexpr int CP = (H >= 64) ? 32 : 16;
    const float* S = (LEVEL == 3) ? g_s3 : (LEVEL == 2) ? g_s2 : g_s1;
    const float* Pprev = (LEVEL == 2) ? (const float*)g_P3 : (const float*)g_P2;
    float* Pout = (LEVEL == 3) ? g_P3 : (LEVEL == 2) ? g_P2 : g_P1;

    __shared__ float Msm[32 * 128];
    __shared__ float Ssm[32 * 64];
    __shared__ float Psm[128 * CP];

    int blk = blockIdx.x;
    int b = blk / (PIX / 64);
    int hw0 = (blk % (PIX / 64)) * 64;
    int tid = threadIdx.x;

    for (int i = tid * 4; i < 32 * 128; i += 512)
        *(float4*)&Msm[i] = *(const float4*)&g_Mt[(LEVEL * 32 + (i >> 7)) * 128 + (i & 127)];
    for (int i = tid * 4; i < 32 * 64; i += 512) {
        int k = i >> 6, p = i & 63;
        *(float4*)&Ssm[i] = *(const float4*)&S[(size_t)(b * 32 + k) * PIX + hw0 + p];
    }
    if (LEVEL < 3) {
        int h = hw0 / H;
        int w0 = hw0 % H;
        int cbase = (h >> 1) * (H / 2) + (w0 >> 1);
        for (int i = tid * 4; i < 128 * CP; i += 512) {
            int o = i / CP, cp = i % CP;
            *(float4*)&Psm[i] = *(const float4*)&Pprev[(size_t)(b * 128 + o) * CPIX + cbase + cp];
        }
    }
    __syncthreads();

    int to = tid >> 3;
    int tp = tid & 7;

    unsigned long long acc[8][4];
#pragma unroll
    for (int i = 0; i < 8; i++)
#pragma unroll
        for (int j = 0; j < 4; j++) acc[i][j] = 0ULL;

#pragma unroll 4
    for (int k = 0; k < 32; k++) {
        float4 ma = *(const float4*)&Msm[k * 128 + to * 8];
        float4 mb = *(const float4*)&Msm[k * 128 + to * 8 + 4];
        float4 sa = *(const float4*)&Ssm[k * 64 + tp * 8];
        float4 sb = *(const float4*)&Ssm[k * 64 + tp * 8 + 4];
        unsigned long long sp[4] = {pk2(sa.x, sa.y), pk2(sa.z, sa.w),
                                    pk2(sb.x, sb.y), pk2(sb.z, sb.w)};
        float mv[8] = {ma.x, ma.y, ma.z, ma.w, mb.x, mb.y, mb.z, mb.w};
#pragma unroll
        for (int o8 = 0; o8 < 8; o8++) {
            unsigned long long md = dup2(mv[o8]);
#pragma unroll
            for (int pp = 0; pp < 4; pp++) acc[o8][pp] = fma2(sp[pp], md, acc[o8][pp]);
        }
    }

    int cpb = (H >= 64) ? tp * 4 : (tp & 3) * 4;
#pragma unroll
    for (int o8 = 0; o8 < 8; o8++) {
        int o = to * 8 + o8;
        float p0 = 0.f, p1 = 0.f, p2 = 0.f, p3 = 0.f;
        if (LEVEL < 3) {
            p0 = Psm[o * CP + cpb + 0];
            p1 = Psm[o * CP + cpb + 1];
            p2 = Psm[o * CP + cpb + 2];
            p3 = Psm[o * CP + cpb + 3];
        }
        float2 v0 = upk2(acc[o8][0]), v1 = upk2(acc[o8][1]);
        float2 v2 = upk2(acc[o8][2]), v3 = upk2(acc[o8][3]);
        float4 r0, r1;
        r0.x = v0.x + p0; r0.y = v0.y + p0; r0.z = v1.x + p1; r0.w = v1.y + p1;
        r1.x = v2.x + p2; r1.y = v2.y + p2; r1.z = v3.x + p3; r1.w = v3.y + p3;
        float* dst = Pout + (size_t)(b * 128 + o) * PIX + hw0 + tp * 8;
        *(float4*)dst = r0;
        *(float4*)(dst + 4) = r1;
    }
}

// ---------------- final (tensor cores; dw0 + level-1 coarse GEMM fused) ----------------
// Tile = 2 fine rows x 64 cols (128 px). 256 thr (8 warps).
// Paired-k smem layout: uint2 rows hold (k, k+4) -> B-fragment fetch = one LDS.64,
// conflict-free (row stride 132/36 uint2 => q-rows on disjoint 8-bank groups).
// P2 patch staged coalesced (float4) into P2sm.
__global__ __launch_bounds__(256) void final_mma(const float* __restrict__ x,
                                                 const float* __restrict__ w_dw,
                                                 const float* __restrict__ b_dw,
                                                 float* __restrict__ out) {
    __shared__ uint2 SfineP[16 * 132];   // 16896 B
    __shared__ uint2 ScrsP[16 * 36];     //  4608 B
    __shared__ float Psm[128 * 34];      // 17408 B
    __shared__ float P2sm[128 * 17];     //  8704 B   (total 47616 <= 48K)
    unsigned* SfineU = (unsigned*)SfineP;
    unsigned* ScrsU = (unsigned*)ScrsP;

    int blk = blockIdx.x;
    int b = blk >> 9;              // 512 tiles per batch
    int rem = blk & 511;
    int h0 = (rem >> 2) * 2;       // even fine-row pair
    int w0 = (rem & 3) * 64;       // 64-col strip
    int tid = threadIdx.x;
    int r2c = h0 >> 2;             // coarse2 row
    int wc2 = w0 >> 2;             // coarse2 col base

    // ---------- Phase 0: dw0 -> SfineP (tf32 pairs), one (channel,row,16-col) job/thread ----------
    {
        int c = tid >> 3;            // 0..31
        int sub = tid & 7;
        int r = sub >> 2;            // row within tile
        int cc0 = (sub & 3) * 16;    // col segment within strip
        int h = h0 + r;
        int base = w0 + cc0;         // 16-aligned global col
        const float* xb = x + (((size_t)(b * 128 + c)) << 16);
        const float* wp = w_dw + c * 9;
        float wk[9];
#pragma unroll
        for (int i = 0; i < 9; i++) wk[i] = wp[i];
        float acc[16];
        float bias = b_dw[c];
#pragma unroll
        for (int j = 0; j < 16; j++) acc[j] = bias;

#pragma unroll
        for (int dy = 0; dy < 3; dy++) {
            int hy = h + dy - 1;
            if (hy >= 0 && hy < 256) {
                const float* row = xb + ((size_t)hy << 8);
                float v[18];
                v[0] = (base > 0) ? row[base - 1] : 0.f;
                float4 C0 = *(const float4*)(row + base);
                float4 C1 = *(const float4*)(row + base + 4);
                float4 C2 = *(const float4*)(row + base + 8);
                float4 C3 = *(const float4*)(row + base + 12);
                v[1] = C0.x;  v[2] = C0.y;  v[3] = C0.z;  v[4] = C0.w;
                v[5] = C1.x;  v[6] = C1.y;  v[7] = C1.z;  v[8] = C1.w;
                v[9] = C2.x;  v[10] = C2.y; v[11] = C2.z; v[12] = C2.w;
                v[13] = C3.x; v[14] = C3.y; v[15] = C3.z; v[16] = C3.w;
                v[17] = (base + 16 < 256) ? row[base + 16] : 0.f;
                float k0 = wk[dy * 3 + 0], k1 = wk[dy * 3 + 1], k2 = wk[dy * 3 + 2];
#pragma unroll
                for (int j = 0; j < 16; j++)
                    acc[j] = fmaf(k0, v[j], fmaf(k1, v[j + 1], fmaf(k2, v[j + 2], acc[j])));
            }
        }
        // pair layout: pair row p = (c>>3)*4 + (c&3); half = (c>>2)&1
        int p = ((c >> 3) << 2) + (c & 3);
        int half = (c >> 2) & 1;
        unsigned* dst = &SfineU[(p * 132 + r * 64 + cc0) * 2 + half];
#pragma unroll
        for (int j = 0; j < 16; j++) dst[j * 2] = f2tf(acc[j]);
    }

    // stage coarse s1 patch (row h0/2, cols w0/2..+31) -> tf32 pairs
    {
        int hc = h0 >> 1, wc0 = w0 >> 1;
        for (int i = tid * 4; i < 32 * 32; i += 1024) {
            int k = i >> 5, cl = i & 31;
            float4 v = *(const float4*)&g_s1[(((size_t)(b * 32 + k)) << 14) +
                                             (size_t)hc * 128 + wc0 + cl];
            int p = ((k >> 3) << 2) + (k & 3);
            int half = (k >> 2) & 1;
            unsigned* db = &ScrsU[(p * 36 + cl) * 2 + half];
            db[0] = f2tf(v.x); db[2] = f2tf(v.y); db[4] = f2tf(v.z); db[6] = f2tf(v.w);
        }
    }

    // stage P2 patch (coalesced float4) -> P2sm[o][0..15]
    for (int i = tid * 4; i < 128 * 16; i += 1024) {
        int o = i >> 4;
        int cc = i & 15;
        float4 v = *(const float4*)&g_P2[(((size_t)(b * 128 + o)) << 12) +
                                         (size_t)r2c * 64 + wc2 + cc];
        float* db = &P2sm[o * 17 + cc];
        db[0] = v.x; db[1] = v.y; db[2] = v.z; db[3] = v.w;
    }
    __syncthreads();

    int lane = tid & 31;
    int warp = tid >> 5;
    int ow = warp << 4;            // 16 outputs per warp
    int r = lane >> 2;             // 0..7
    int q = lane & 3;              // 0..3
    int oa = ow + r, ob = oa + 8;

    // ---------- Phase A: coarse GEMM (M columns 32..63 vs s1) ----------
    {
        unsigned ac[4][4];
#pragma unroll
        for (int kk = 0; kk < 4; kk++) {
            const float* m0 = &g_M[oa * 128 + 32 + kk * 8 + q];
            const float* m1 = &g_M[ob * 128 + 32 + kk * 8 + q];
            ac[kk][0] = f2tf(m0[0]);
            ac[kk][1] = f2tf(m1[0]);
            ac[kk][2] = f2tf(m0[4]);
            ac[kk][3] = f2tf(m1[4]);
        }
        float dva = g_d[oa], dvb = g_d[ob];
#pragma unroll
        for (int nc = 0; nc < 4; nc++) {
            float c0 = 0.f, c1 = 0.f, c2 = 0.f, c3 = 0.f;
#pragma unroll
            for (int kk = 0; kk < 4; kk++) {
                uint2 bv = ScrsP[(kk * 4 + q) * 36 + nc * 8 + r];
                mma_tf32(c0, c1, c2, c3, ac[kk][0], ac[kk][1], ac[kk][2], ac[kk][3],
                         bv.x, bv.y);
            }
            float pa = P2sm[oa * 17 + nc * 4 + q] + dva;   // both children share coarse2 parent
            float pb = P2sm[ob * 17 + nc * 4 + q] + dvb;
            float2 va, vb;
            va.x = c0 + pa; va.y = c1 + pa;
            vb.x = c2 + pb; vb.y = c3 + pb;
            *(float2*)&Psm[oa * 34 + nc * 8 + q * 2] = va;
            *(float2*)&Psm[ob * 34 + nc * 8 + q * 2] = vb;
        }
    }

    // A fragments for fine GEMM (M columns 0..31)
    unsigned a[4][4];
#pragma unroll
    for (int kk = 0; kk < 4; kk++) {
        const float* m0 = &g_M[oa * 128 + kk * 8 + q];
        const float* m1 = &g_M[ob * 128 + kk * 8 + q];
        a[kk][0] = f2tf(m0[0]);
        a[kk][1] = f2tf(m1[0]);
        a[kk][2] = f2tf(m0[4]);
        a[kk][3] = f2tf(m1[4]);
    }
    __syncthreads();

    // ---------- Phase B: fine GEMM + epilogue ----------
    size_t xbase_a = (((size_t)(b * 128 + oa)) << 16);
    size_t xbase_b = (((size_t)(b * 128 + ob)) << 16);

#pragma unroll 4
    for (int n = 0; n < 16; n++) {
        float c0 = 0.f, c1 = 0.f, c2 = 0.f, c3 = 0.f;
#pragma unroll
        for (int kk = 0; kk < 4; kk++) {
            uint2 bv = SfineP[(kk * 4 + q) * 132 + n * 8 + r];
            mma_tf32(c0, c1, c2, c3, a[kk][0], a[kk][1], a[kk][2], a[kk][3], bv.x, bv.y);
        }
        int rowb = n >> 3;                       // fine row within tile
        int coln = (n & 7) * 8 + q * 2;          // fine col within strip (even)
        size_t roff = (size_t)(h0 + rowb) * 256 + w0 + coln;
        float pa = Psm[oa * 34 + (n & 7) * 4 + q];   // coarse col = coln/2
        float pb = Psm[ob * 34 + (n & 7) * 4 + q];
        float2 xa = *(const float2*)&x[xbase_a + roff];
        float2 xb = *(const float2*)&x[xbase_b + roff];
        float2 ra, rb;
        ra.x = gelu_mul(c0 + pa, xa.x);
        ra.y = gelu_mul(c1 + pa, xa.y);
        rb.x = gelu_mul(c2 + pb, xb.x);
        rb.y = gelu_mul(c3 + pb, xb.y);
        *(float2*)&out[xbase_a + roff] = ra;
        *(float2*)&out[xbase_b + roff] = rb;
    }
}

// ---------------- launch ----------------
extern "C" void kernel_launch(void* const* d_in, const int* in_sizes, int n_in,
                              void* d_out, int out_size) {
    const float* x   = (const float*)d_in[0];
    const float* wdw = (const float*)d_in[1];
    const float* bdw = (const float*)d_in[2];
    const float* w1  = (const float*)d_in[3];
    const float* b1  = (const float*)d_in[4];
    const float* w2  = (const float*)d_in[5];
    const float* b2  = (const float*)d_in[6];
    const float* w3  = (const float*)d_in[7];
    const float* b3  = (const float*)d_in[8];
    float* out = (float*)d_out;

    setup1_kernel<<<96, 96>>>(w1, b1, w2, b2);
    setup2_kernel<<<128, 128>>>(w3, b3);

    pooldw_kernel<1, 2, 128><<<BATCH * 32 * 16, 256>>>(x, wdw, bdw);
    pooldw_kernel<2, 4, 64><<<BATCH * 32 * 8, 256>>>(x, wdw, bdw);
    pooldw_kernel<3, 8, 32><<<BATCH * 32 * 4, 256>>>(x, wdw, bdw);

    gemm_tiled<3, 32><<<BATCH * (32 * 32 / 64), 128>>>();
    gemm_tiled<2, 64><<<BATCH * (64 * 64 / 64), 128>>>();

    final_mma<<<BATCH * 512, 256>>>(x, wdw, bdw, out);
}